// round 2
// baseline (speedup 1.0000x reference)
#include <cuda_runtime.h>

// Problem constants (fixed by setup_inputs):
// B=4, C=64, K=16, N=16384, W_OUT=16, C_OUT=64
#define NB 4
#define NC 64
#define NN 16384
#define MT 64          // points per CTA
#define NCTA 1024      // NB * NN / MT  (4 * 16384 / 64)
#define OUT_ELEMS (NB * NC * NN)   // 4194304

// Deterministic scratch (no atomics): per-CTA per-channel partial sums.
__device__ float g_psum[NCTA * NC];
__device__ float g_psq[NCTA * NC];
__device__ float g_bn[2 * NC];   // [0..63] scale, [64..127] shift

// ---------------------------------------------------------------------------
// Kernel 1: fused weightnet + per-point (C x K)@(K x 16) + 1024->64 linear.
// CTA handles 64 consecutive points of one batch. 256 threads.
// smem: P_s[64 rows][64 m] | t_s[64 kk][64 m] | lw_s[64 o][64 kk]  = 48KB
// ---------------------------------------------------------------------------
__global__ __launch_bounds__(256) void sc_k1(
    const float* __restrict__ points,   // [B,64,16,N]
    const float* __restrict__ coord,    // [B,3,16,N]
    const float* __restrict__ w1,       // [16,3]
    const float* __restrict__ b1,       // [16]
    const float* __restrict__ lin_w,    // [64,1024]
    const float* __restrict__ lin_b,    // [64]
    float* __restrict__ outp)           // [B,64,N] pre-BN
{
    __shared__ float sm[12288];         // 48KB
    float* P_s  = sm;                   // 4096 floats: [(ci*16+k)*64 + m]
    float* t_s  = sm + 4096;            // 4096 floats: [kk*64 + m]
    float* lw_s = sm + 8192;            // 4096 floats: [o*64 + kk]
    float* coord_s = sm;                // alias of P_s: 3072 floats [(d*16+k)*64 + m]

    const int tid = threadIdx.x;
    const int bx  = blockIdx.x;
    const int b   = bx >> 8;            // 256 tiles per batch, 4 batches
    const int n0  = (bx & 255) << 6;

    // ---- stage coordinates (coalesced float4) ----
    {
        const float4* g = reinterpret_cast<const float4*>(coord);
        float4* dst = reinterpret_cast<float4*>(coord_s);
#pragma unroll
        for (int s = 0; s < 3; s++) {
            int fi  = tid + 256 * s;        // 0..767
            int row = fi >> 4;              // d*16+k, 0..47
            int c4  = fi & 15;
            dst[fi] = g[(b * 48 + row) * (NN / 4) + (n0 >> 2) + c4];
        }
    }
    __syncthreads();

    // ---- weightnet W into registers: thread (m, og) owns W[og*4+oo][k] ----
    const int m  = tid & 63;
    const int og = tid >> 6;     // 0..3
    float wreg[4][16];
    {
        float w1r[4][3], b1r[4];
#pragma unroll
        for (int oo = 0; oo < 4; oo++) {
            int o = og * 4 + oo;
            w1r[oo][0] = w1[o * 3 + 0];
            w1r[oo][1] = w1[o * 3 + 1];
            w1r[oo][2] = w1[o * 3 + 2];
            b1r[oo]    = b1[o];
        }
#pragma unroll
        for (int k = 0; k < 16; k++) {
            float c0 = coord_s[(k) * 64 + m];
            float c1 = coord_s[(16 + k) * 64 + m];
            float c2 = coord_s[(32 + k) * 64 + m];
#pragma unroll
            for (int oo = 0; oo < 4; oo++) {
                float v = fmaf(w1r[oo][2], c2,
                          fmaf(w1r[oo][1], c1,
                          fmaf(w1r[oo][0], c0, b1r[oo])));
                wreg[oo][k] = fmaxf(v, 0.0f);
            }
        }
    }

    // ---- GEMM thread mapping: (tm, to); 4x4 register tile ----
    const int tm = tid & 15;     // m = tm + 16*i
    const int to = tid >> 4;     // o = to + 16*j
    float acc[4][4] = {};

    for (int cc0 = 0; cc0 < 64; cc0 += 4) {   // 16 channel chunks
        __syncthreads();   // previous-iteration smem reads done
        // stage P chunk + lin_w chunk (coalesced float4, conflict-free STS)
        {
            const float4* gp = reinterpret_cast<const float4*>(points);
            const float4* gl = reinterpret_cast<const float4*>(lin_w);
            float4* pd = reinterpret_cast<float4*>(P_s);
            float4* ld = reinterpret_cast<float4*>(lw_s);
#pragma unroll
            for (int s = 0; s < 4; s++) {
                int fi  = tid + 256 * s;     // 0..1023
                int row = fi >> 4;           // 0..63
                int c4  = fi & 15;
                // points[(b*1024 + cc0*16 + row)*16384 + n0 + 4*c4]
                pd[fi] = gp[(b * 1024 + cc0 * 16 + row) * (NN / 4) + (n0 >> 2) + c4];
                // lin_w[row][cc0*16 + 4*c4]   -> lw_s[row*64 + 4*c4]
                ld[fi] = gl[row * 256 + cc0 * 4 + c4];
            }
        }
        __syncthreads();

        // ---- t-compute: t_s[(ci*16+o')*64 + m] ----
#pragma unroll
        for (int ci = 0; ci < 4; ci++) {
            float a0 = 0.f, a1 = 0.f, a2 = 0.f, a3 = 0.f;
#pragma unroll
            for (int k = 0; k < 16; k++) {
                float p = P_s[(ci * 16 + k) * 64 + m];
                a0 = fmaf(p, wreg[0][k], a0);
                a1 = fmaf(p, wreg[1][k], a1);
                a2 = fmaf(p, wreg[2][k], a2);
                a3 = fmaf(p, wreg[3][k], a3);
            }
            int jb = (ci * 16 + og * 4) * 64 + m;
            t_s[jb]       = a0;
            t_s[jb + 64]  = a1;
            t_s[jb + 128] = a2;
            t_s[jb + 192] = a3;
        }
        __syncthreads();

        // ---- GEMM: acc[m][o] += t_s[kk][m] * lw_s[o][kk] ----
#pragma unroll 4
        for (int kk = 0; kk < 64; kk++) {
            float tv0 = t_s[kk * 64 + tm];
            float tv1 = t_s[kk * 64 + tm + 16];
            float tv2 = t_s[kk * 64 + tm + 32];
            float tv3 = t_s[kk * 64 + tm + 48];
            float lv0 = lw_s[to * 64 + kk];
            float lv1 = lw_s[(to + 16) * 64 + kk];
            float lv2 = lw_s[(to + 32) * 64 + kk];
            float lv3 = lw_s[(to + 48) * 64 + kk];
            acc[0][0] = fmaf(tv0, lv0, acc[0][0]);
            acc[1][0] = fmaf(tv1, lv0, acc[1][0]);
            acc[2][0] = fmaf(tv2, lv0, acc[2][0]);
            acc[3][0] = fmaf(tv3, lv0, acc[3][0]);
            acc[0][1] = fmaf(tv0, lv1, acc[0][1]);
            acc[1][1] = fmaf(tv1, lv1, acc[1][1]);
            acc[2][1] = fmaf(tv2, lv1, acc[2][1]);
            acc[3][1] = fmaf(tv3, lv1, acc[3][1]);
            acc[0][2] = fmaf(tv0, lv2, acc[0][2]);
            acc[1][2] = fmaf(tv1, lv2, acc[1][2]);
            acc[2][2] = fmaf(tv2, lv2, acc[2][2]);
            acc[3][2] = fmaf(tv3, lv2, acc[3][2]);
            acc[0][3] = fmaf(tv0, lv3, acc[0][3]);
            acc[1][3] = fmaf(tv1, lv3, acc[1][3]);
            acc[2][3] = fmaf(tv2, lv3, acc[2][3]);
            acc[3][3] = fmaf(tv3, lv3, acc[3][3]);
        }
    }

    // ---- epilogue: +lin_b, write pre-BN, deterministic channel partials ----
    float lbr[4];
#pragma unroll
    for (int j = 0; j < 4; j++) lbr[j] = lin_b[to + 16 * j];

    float sj[4], qj[4];
#pragma unroll
    for (int j = 0; j < 4; j++) {
        int o = to + 16 * j;
        float ss = 0.f, qq = 0.f;
#pragma unroll
        for (int i = 0; i < 4; i++) {
            float x = acc[i][j] + lbr[j];
            outp[((b * 64 + o) << 14) + n0 + tm + 16 * i] = x;
            ss += x;
            qq += x * x;
        }
        // reduce across tm (lane bits 0..3); to lives in lane bit 4 -> untouched
#pragma unroll
        for (int d = 8; d; d >>= 1) {
            ss += __shfl_xor_sync(0xffffffffu, ss, d);
            qq += __shfl_xor_sync(0xffffffffu, qq, d);
        }
        sj[j] = ss;
        qj[j] = qq;
    }
    if (tm == 0) {
#pragma unroll
        for (int j = 0; j < 4; j++) {
            int o = to + 16 * j;
            g_psum[bx * 64 + o] = sj[j];
            g_psq[bx * 64 + o]  = qj[j];
        }
    }
}

// ---------------------------------------------------------------------------
// Kernel 2: reduce 1024 partials per channel -> BN scale/shift (deterministic)
// ---------------------------------------------------------------------------
__global__ void sc_k2(const float* __restrict__ gamma,
                      const float* __restrict__ beta)
{
    const int ch = blockIdx.x;       // 64 blocks
    const int r  = threadIdx.x;      // 128 threads
    float s = 0.f, q = 0.f;
    for (int c = r; c < NCTA; c += 128) {
        s += g_psum[c * 64 + ch];
        q += g_psq[c * 64 + ch];
    }
    __shared__ float ss[128], qs[128];
    ss[r] = s; qs[r] = q;
    __syncthreads();
    for (int d = 64; d; d >>= 1) {
        if (r < d) { ss[r] += ss[r + d]; qs[r] += qs[r + d]; }
        __syncthreads();
    }
    if (r == 0) {
        const float inv = 1.0f / (float)(NB * NN);
        float mean = ss[0] * inv;
        float var  = qs[0] * inv - mean * mean;
        float sc   = gamma[ch] * rsqrtf(var + 1e-5f);
        g_bn[ch]      = sc;
        g_bn[64 + ch] = beta[ch] - mean * sc;
    }
}

// ---------------------------------------------------------------------------
// Kernel 3: in-place BN + ReLU over [B,64,N], float4 vectorized.
// ---------------------------------------------------------------------------
__global__ void sc_k3(float* __restrict__ outp)
{
    int i4 = blockIdx.x * blockDim.x + threadIdx.x;   // 1048576 float4
    int ch = (i4 >> 12) & 63;                          // (flat>>14)&63
    float sc = g_bn[ch];
    float sh = g_bn[64 + ch];
    float4 v = reinterpret_cast<float4*>(outp)[i4];
    v.x = fmaxf(fmaf(v.x, sc, sh), 0.0f);
    v.y = fmaxf(fmaf(v.y, sc, sh), 0.0f);
    v.z = fmaxf(fmaf(v.z, sc, sh), 0.0f);
    v.w = fmaxf(fmaf(v.w, sc, sh), 0.0f);
    reinterpret_cast<float4*>(outp)[i4] = v;
}

// ---------------------------------------------------------------------------
extern "C" void kernel_launch(void* const* d_in, const int* in_sizes, int n_in,
                              void* d_out, int out_size)
{
    const float* xyz    = (const float*)d_in[0];
    const float* points = (const float*)d_in[1];
    const float* coord  = (const float*)d_in[2];
    const float* w1     = (const float*)d_in[3];
    const float* b1     = (const float*)d_in[4];
    const float* lin_w  = (const float*)d_in[5];
    const float* lin_b  = (const float*)d_in[6];
    const float* gamma  = (const float*)d_in[7];
    const float* beta   = (const float*)d_in[8];

    float* out = (float*)d_out;
    // Output is (xyz, new_points) concatenated; be robust if xyz is absent.
    int off = out_size - OUT_ELEMS;
    if (off < 0) off = 0;
    float* outp = out + off;

    if (off > 0) {
        cudaMemcpyAsync(out, xyz, (size_t)off * sizeof(float),
                        cudaMemcpyDeviceToDevice);
    }
    sc_k1<<<NCTA, 256>>>(points, coord, w1, b1, lin_w, lin_b, outp);
    sc_k2<<<64, 128>>>(gamma, beta);
    sc_k3<<<OUT_ELEMS / 4 / 256, 256>>>(outp);
}

// round 3
// speedup vs baseline: 1.0373x; 1.0373x over previous
#include <cuda_runtime.h>

// Problem constants: B=4, C=64, K=16, N=16384, W_OUT=16, C_OUT=64
#define NB 4
#define NC 64
#define NN 16384
#define NCTA 1024               // NB*NN/64 points per CTA
#define OUT_ELEMS (NB * NC * NN)
#define CH 2                    // channels per chunk
#define KKC (CH * 16)           // 32 kk per chunk
#define NCHUNK (NC / CH)        // 32 chunks

// Deterministic scratch
__device__ float  g_psum[NCTA * NC];
__device__ float  g_psq[NCTA * NC];
__device__ float  g_bn[2 * NC];
__device__ float2 g_lwD[1024 * 64];   // lin_w transposed+duplicated: [k][o] = (v,v)

typedef unsigned long long ull;

static __device__ __forceinline__ ull ffma2(ull a, ull b, ull c) {
    ull d;
    asm("fma.rn.f32x2 %0, %1, %2, %3;" : "=l"(d) : "l"(a), "l"(b), "l"(c));
    return d;
}
static __device__ __forceinline__ ull pack2(float lo, float hi) {
    ull d;
    asm("mov.b64 %0, {%1, %2};" : "=l"(d)
        : "r"(__float_as_uint(lo)), "r"(__float_as_uint(hi)));
    return d;
}
static __device__ __forceinline__ ull dup2(float v) {
    ull d;
    unsigned u = __float_as_uint(v);
    asm("mov.b64 %0, {%1, %2};" : "=l"(d) : "r"(u), "r"(u));
    return d;
}
static __device__ __forceinline__ float2 unpk(ull v) {
    unsigned a, b;
    asm("mov.b64 {%0, %1}, %2;" : "=r"(a), "=r"(b) : "l"(v));
    return make_float2(__uint_as_float(a), __uint_as_float(b));
}

// t_s banked layout: float index for (kk, m), m in 0..63.
// float4 slot s = (m&4 ? 8:0) + (m>>3), component m&3  -> two contiguous
// half-arrays so GEMM LDS.128 across lanes is conflict-free.
static __device__ __forceinline__ int t_idx(int kk, int m) {
    return kk * 64 + ((m & 4) << 3) + ((m >> 3) << 2) + (m & 3);
}

// ---------------------------------------------------------------------------
// Kernel 0: transpose + duplicate lin_w [64][1024] -> g_lwD[k][o] = (v,v)
// ---------------------------------------------------------------------------
__global__ void sc_k0(const float* __restrict__ lin_w) {
    __shared__ float t[32][33];
    int k0 = blockIdx.x * 32, o0 = blockIdx.y * 32;
    int tx = threadIdx.x, ty = threadIdx.y;       // 32 x 8
#pragma unroll
    for (int i = 0; i < 32; i += 8)
        t[ty + i][tx] = lin_w[(o0 + ty + i) * 1024 + k0 + tx];   // t[o][k]
    __syncthreads();
#pragma unroll
    for (int i = 0; i < 32; i += 8) {
        float v = t[tx][ty + i];                  // o = o0+tx, k = k0+ty+i
        g_lwD[(k0 + ty + i) * 64 + o0 + tx] = make_float2(v, v);
    }
}

// ---------------------------------------------------------------------------
// Kernel 1: fused weightnet + per-point CxK@Kx16 + 1024->64 linear (f32x2).
// CTA = 64 points, 256 threads. smem 32KB static:
//   P_s [32 rows][64 m] | t_s [32 kk][64 m banked] | lw_d [32 kk][64 o] float2
// GEMM thread tile: 8 m x 2 o  (tm = tid&7 -> m = 8*tm.., to = tid>>3 -> o=2*to..)
// ---------------------------------------------------------------------------
__global__ __launch_bounds__(256) void sc_k1(
    const float* __restrict__ points,   // [B,64,16,N]
    const float* __restrict__ coord,    // [B,3,16,N]
    const float* __restrict__ w1,       // [16,3]
    const float* __restrict__ b1,       // [16]
    const float* __restrict__ lin_b,    // [64]
    float* __restrict__ outp)           // [B,64,N] pre-BN
{
    __shared__ float sm[8192];           // 32KB
    float* P_s  = sm;                    // 2048 floats
    float* t_s  = sm + 2048;             // 2048 floats
    float* lw_d = sm + 4096;             // 4096 floats (2048 float2)
    float* coord_s = sm;                 // alias, prologue only (3072 floats)

    const int tid = threadIdx.x;
    const int bx  = blockIdx.x;
    const int b   = bx >> 8;
    const int n0  = (bx & 255) << 6;

    // ---- stage coordinates (coalesced float4) ----
    {
        const float4* g = reinterpret_cast<const float4*>(coord);
        float4* dst = reinterpret_cast<float4*>(coord_s);
#pragma unroll
        for (int s = 0; s < 3; s++) {
            int fi  = tid + 256 * s;        // 0..767
            int row = fi >> 4;              // d*16+k
            int c4  = fi & 15;
            dst[fi] = g[(b * 48 + row) * (NN / 4) + (n0 >> 2) + c4];
        }
    }
    __syncthreads();

    // ---- weightnet: thread (m, og) owns packed W pairs wq[g][k] ----
    const int m  = tid & 63;
    const int og = tid >> 6;     // 0..3 -> o' = og*4 + 2g + h
    ull wq[2][16];
    {
        float w1r[4][3], b1r[4];
#pragma unroll
        for (int oo = 0; oo < 4; oo++) {
            int o = og * 4 + oo;
            w1r[oo][0] = w1[o * 3 + 0];
            w1r[oo][1] = w1[o * 3 + 1];
            w1r[oo][2] = w1[o * 3 + 2];
            b1r[oo]    = b1[o];
        }
#pragma unroll
        for (int k = 0; k < 16; k++) {
            float c0 = coord_s[(k) * 64 + m];
            float c1 = coord_s[(16 + k) * 64 + m];
            float c2 = coord_s[(32 + k) * 64 + m];
            float v[4];
#pragma unroll
            for (int oo = 0; oo < 4; oo++) {
                float t = fmaf(w1r[oo][2], c2,
                          fmaf(w1r[oo][1], c1,
                          fmaf(w1r[oo][0], c0, b1r[oo])));
                v[oo] = fmaxf(t, 0.0f);
            }
            wq[0][k] = pack2(v[0], v[1]);
            wq[1][k] = pack2(v[2], v[3]);
        }
    }

    // ---- GEMM thread mapping ----
    const int tm = tid & 7;      // m = 8*tm + (0..7)
    const int to = tid >> 3;     // o = 2*to + (0..1)
    ull acc[4][2];
#pragma unroll
    for (int q = 0; q < 4; q++) { acc[q][0] = 0ull; acc[q][1] = 0ull; }

    const float4* gp = reinterpret_cast<const float4*>(points);
    const float4* gl = reinterpret_cast<const float4*>(g_lwD);
    float4* pd = reinterpret_cast<float4*>(P_s);
    float4* ld = reinterpret_cast<float4*>(lw_d);
    const ulonglong2* t2  = reinterpret_cast<const ulonglong2*>(t_s);
    const ulonglong2* l2p = reinterpret_cast<const ulonglong2*>(lw_d);

    for (int cc0 = 0; cc0 < NC; cc0 += CH) {     // 32 chunks
        __syncthreads();
        // ---- stage P chunk (512 f4) + lw_d chunk (1024 f4) ----
#pragma unroll
        for (int s = 0; s < 2; s++) {
            int fi  = tid + 256 * s;             // 0..511
            int row = fi >> 4;                   // 0..31
            int c4  = fi & 15;
            pd[fi] = gp[(b * 1024 + cc0 * 16 + row) * (NN / 4) + (n0 >> 2) + c4];
        }
#pragma unroll
        for (int s = 0; s < 4; s++) {
            int fi = tid + 256 * s;              // 0..1023
            ld[fi] = gl[cc0 * 512 + fi];
        }
        __syncthreads();

        // ---- t-compute (f32x2 over o'-pairs) ----
#pragma unroll
        for (int ci = 0; ci < CH; ci++) {
            ull a0 = 0ull, a1 = 0ull;
#pragma unroll
            for (int k = 0; k < 16; k++) {
                ull pp = dup2(P_s[(ci * 16 + k) * 64 + m]);
                a0 = ffma2(pp, wq[0][k], a0);
                a1 = ffma2(pp, wq[1][k], a1);
            }
            int kk = ci * 16 + og * 4;           // chunk-local
            float2 v0 = unpk(a0), v1 = unpk(a1);
            t_s[t_idx(kk + 0, m)] = v0.x;
            t_s[t_idx(kk + 1, m)] = v0.y;
            t_s[t_idx(kk + 2, m)] = v1.x;
            t_s[t_idx(kk + 3, m)] = v1.y;
        }
        __syncthreads();

        // ---- GEMM: acc[q][j] += t(m-pair q) * lw(o=2to+j) ----
#pragma unroll 4
        for (int kk = 0; kk < KKC; kk++) {
            ulonglong2 ta = t2[kk * 16 + tm];        // m pairs (0,1),(2,3)
            ulonglong2 tb = t2[kk * 16 + 8 + tm];    // m pairs (4,5),(6,7)
            ulonglong2 lw = l2p[kk * 32 + to];       // dup(o0), dup(o1)
            acc[0][0] = ffma2(ta.x, lw.x, acc[0][0]);
            acc[1][0] = ffma2(ta.y, lw.x, acc[1][0]);
            acc[2][0] = ffma2(tb.x, lw.x, acc[2][0]);
            acc[3][0] = ffma2(tb.y, lw.x, acc[3][0]);
            acc[0][1] = ffma2(ta.x, lw.y, acc[0][1]);
            acc[1][1] = ffma2(ta.y, lw.y, acc[1][1]);
            acc[2][1] = ffma2(tb.x, lw.y, acc[2][1]);
            acc[3][1] = ffma2(tb.y, lw.y, acc[3][1]);
        }
    }

    // ---- epilogue: +lin_b, float4 stores, deterministic channel partials ----
#pragma unroll
    for (int j = 0; j < 2; j++) {
        int o = 2 * to + j;
        float lb = lin_b[o];
        float2 p0 = unpk(acc[0][j]);
        float2 p1 = unpk(acc[1][j]);
        float2 p2 = unpk(acc[2][j]);
        float2 p3 = unpk(acc[3][j]);
        float4 va = make_float4(p0.x + lb, p0.y + lb, p1.x + lb, p1.y + lb);
        float4 vb = make_float4(p2.x + lb, p2.y + lb, p3.x + lb, p3.y + lb);
        float* row = outp + ((b * 64 + o) << 14) + n0 + 8 * tm;
        reinterpret_cast<float4*>(row)[0] = va;
        reinterpret_cast<float4*>(row)[1] = vb;
        float ss = va.x + va.y + va.z + va.w + vb.x + vb.y + vb.z + vb.w;
        float qq = va.x * va.x + va.y * va.y + va.z * va.z + va.w * va.w
                 + vb.x * vb.x + vb.y * vb.y + vb.z * vb.z + vb.w * vb.w;
#pragma unroll
        for (int d = 4; d; d >>= 1) {     // reduce across tm (lane bits 0..2)
            ss += __shfl_xor_sync(0xffffffffu, ss, d);
            qq += __shfl_xor_sync(0xffffffffu, qq, d);
        }
        if (tm == 0) {
            g_psum[bx * 64 + o] = ss;
            g_psq[bx * 64 + o]  = qq;
        }
    }
}

// ---------------------------------------------------------------------------
// Kernel 2: reduce 1024 partials per channel -> BN scale/shift
// ---------------------------------------------------------------------------
__global__ void sc_k2(const float* __restrict__ gamma,
                      const float* __restrict__ beta)
{
    const int ch = blockIdx.x;
    const int r  = threadIdx.x;      // 128
    float s = 0.f, q = 0.f;
    for (int c = r; c < NCTA; c += 128) {
        s += g_psum[c * 64 + ch];
        q += g_psq[c * 64 + ch];
    }
    __shared__ float ss[128], qs[128];
    ss[r] = s; qs[r] = q;
    __syncthreads();
    for (int d = 64; d; d >>= 1) {
        if (r < d) { ss[r] += ss[r + d]; qs[r] += qs[r + d]; }
        __syncthreads();
    }
    if (r == 0) {
        const float inv = 1.0f / (float)(NB * NN);
        float mean = ss[0] * inv;
        float var  = qs[0] * inv - mean * mean;
        float sc   = gamma[ch] * rsqrtf(var + 1e-5f);
        g_bn[ch]      = sc;
        g_bn[64 + ch] = beta[ch] - mean * sc;
    }
}

// ---------------------------------------------------------------------------
// Kernel 3: in-place BN + ReLU, float4
// ---------------------------------------------------------------------------
__global__ void sc_k3(float* __restrict__ outp)
{
    int i4 = blockIdx.x * blockDim.x + threadIdx.x;
    int ch = (i4 >> 12) & 63;
    float sc = g_bn[ch];
    float sh = g_bn[64 + ch];
    float4 v = reinterpret_cast<float4*>(outp)[i4];
    v.x = fmaxf(fmaf(v.x, sc, sh), 0.0f);
    v.y = fmaxf(fmaf(v.y, sc, sh), 0.0f);
    v.z = fmaxf(fmaf(v.z, sc, sh), 0.0f);
    v.w = fmaxf(fmaf(v.w, sc, sh), 0.0f);
    reinterpret_cast<float4*>(outp)[i4] = v;
}

// ---------------------------------------------------------------------------
extern "C" void kernel_launch(void* const* d_in, const int* in_sizes, int n_in,
                              void* d_out, int out_size)
{
    const float* xyz    = (const float*)d_in[0];
    const float* points = (const float*)d_in[1];
    const float* coord  = (const float*)d_in[2];
    const float* w1     = (const float*)d_in[3];
    const float* b1     = (const float*)d_in[4];
    const float* lin_w  = (const float*)d_in[5];
    const float* lin_b  = (const float*)d_in[6];
    const float* gamma  = (const float*)d_in[7];
    const float* beta   = (const float*)d_in[8];

    float* out = (float*)d_out;
    int off = out_size - OUT_ELEMS;
    if (off < 0) off = 0;
    float* outp = out + off;

    if (off > 0) {
        cudaMemcpyAsync(out, xyz, (size_t)off * sizeof(float),
                        cudaMemcpyDeviceToDevice);
    }
    sc_k0<<<dim3(32, 2), dim3(32, 8)>>>(lin_w);
    sc_k1<<<NCTA, 256>>>(points, coord, w1, b1, lin_b, outp);
    sc_k2<<<64, 128>>>(gamma, beta);
    sc_k3<<<OUT_ELEMS / 4 / 256, 256>>>(outp);
}

// round 6
// speedup vs baseline: 3.1871x; 3.0725x over previous
#include <cuda_runtime.h>
#include <cuda_bf16.h>
#include <stdint.h>

// B=4, C=64, K=16, N=16384, W_OUT=16, C_OUT=64
#define NB 4
#define NC 64
#define NN 16384
#define NCTA 1024                // 64 points per CTA
#define OUT_ELEMS (NB * NC * NN)
#define NCHUNK 16                // 4 channels/chunk -> kk=64

// ---- dynamic smem layout (bytes) ----
#define SM_LB    0                   // 64 floats
#define SM_AHI   1024                // 64 m x 128B (64 kk bf16) = 8KB
#define SM_ALO   (SM_AHI + 8192)
#define SM_B0H   (SM_ALO + 8192)     // 64 n x 128B = 8KB
#define SM_B0L   (SM_B0H + 8192)
#define SM_B1H   (SM_B0L + 8192)
#define SM_B1L   (SM_B1H + 8192)
#define SM_P0    (SM_B1L + 8192)     // 64 rows x 256B = 16KB
#define SM_P1    (SM_P0 + 16384)
#define SM_TOTAL (SM_P1 + 16384)     // 82944 B
// epilogue aliases
#define SM_DS    SM_P0               // 64 o x 68 floats = 17408 B (spills into P1, free)
#define SM_PART  SM_B0H              // 2 x 8 x 64 floats

__device__ float g_psum[NCTA * NC];
__device__ float g_psq[NCTA * NC];
__device__ float g_bn[2 * NC];
__device__ __align__(16) __nv_bfloat16 g_lw_hi[NC * 1024];  // [o][k]
__device__ __align__(16) __nv_bfloat16 g_lw_lo[NC * 1024];

#define SWZ(x) ((x) ^ (((x) >> 3) & 0x70))

static __device__ __forceinline__ uint32_t s2u(const void* p) {
    uint32_t a;
    asm("{ .reg .u64 t; cvta.to.shared.u64 t, %1; cvt.u32.u64 %0, t; }"
        : "=r"(a) : "l"(p));
    return a;
}
static __device__ __forceinline__ void cpa16(uint32_t dst, const void* src) {
    asm volatile("cp.async.cg.shared.global [%0], [%1], 16;"
                 :: "r"(dst), "l"(src) : "memory");
}
static __device__ __forceinline__ void cpa_commit() {
    asm volatile("cp.async.commit_group;" ::: "memory");
}
static __device__ __forceinline__ void cpa_wait0() {
    asm volatile("cp.async.wait_group 0;" ::: "memory");
}

#define LDSM4(r0, r1, r2, r3, addr)                                          \
    asm volatile("ldmatrix.sync.aligned.m8n8.x4.shared.b16 {%0,%1,%2,%3}, [%4];" \
                 : "=r"(r0), "=r"(r1), "=r"(r2), "=r"(r3) : "r"(addr))

#define MMA16816(d, a0, a1, a2, a3, b0, b1)                                  \
    asm volatile("mma.sync.aligned.m16n8k16.row.col.f32.bf16.bf16.f32 "      \
                 "{%0,%1,%2,%3}, {%4,%5,%6,%7}, {%8,%9}, {%0,%1,%2,%3};"     \
                 : "+f"(d[0]), "+f"(d[1]), "+f"(d[2]), "+f"(d[3])            \
                 : "r"(a0), "r"(a1), "r"(a2), "r"(a3), "r"(b0), "r"(b1))

// ---------------------------------------------------------------------------
// k0: lin_w fp32 -> bf16 hi/lo tables, [o][k] k-major
// ---------------------------------------------------------------------------
__global__ void sc_k0(const float* __restrict__ lin_w) {
    int o = blockIdx.x;
    for (int k = threadIdx.x; k < 1024; k += 256) {
        float f = lin_w[o * 1024 + k];
        __nv_bfloat16 h = __float2bfloat16(f);
        float r = f - __bfloat162float(h);
        g_lw_hi[o * 1024 + k] = h;
        g_lw_lo[o * 1024 + k] = __float2bfloat16(r);
    }
}

// ---------------------------------------------------------------------------
// k1: fused weightnet + t-compute + bf16-split mma.sync GEMM + BN partials
// CTA = 64 points, 512 threads (16 warps, 4x4 warp grid, warp tile 16x16).
// ---------------------------------------------------------------------------
__global__ __launch_bounds__(512, 1)
void sc_k1(const float* __restrict__ points,   // [B,64,16,N]
           const float* __restrict__ coord,    // [B,3,16,N]
           const float* __restrict__ w1,       // [16,3]
           const float* __restrict__ b1,       // [16]
           const float* __restrict__ lin_b,    // [64]
           float* __restrict__ outp)           // [B,64,N] pre-BN
{
    extern __shared__ char smem[];
    const uint32_t sb = s2u(smem);
    const int tid  = threadIdx.x;
    const int lane = tid & 31;
    const int wid  = tid >> 5;
    const int bx   = blockIdx.x;
    const int b    = bx >> 8;             // 256 tiles per batch
    const int n0   = (bx & 255) << 6;

    if (tid < 64) ((float*)(smem + SM_LB))[tid] = lin_b[tid];

    // ---- prologue cp.async: coord -> P1, P(0) -> P0, B(0) -> B0 ----
#pragma unroll
    for (int s = 0; s < 2; s++) {
        int fi = tid + 512 * s;           // coord: 768 x 16B
        if (fi < 768) {
            int row = fi >> 4, seg = fi & 15;
            cpa16(sb + SM_P1 + row * 256 + seg * 16,
                  coord + (size_t)(b * 48 + row) * NN + n0 + seg * 4);
        }
    }
#pragma unroll
    for (int s = 0; s < 2; s++) {
        int fi = tid + 512 * s;           // P: 1024 x 16B
        int row = fi >> 4, seg = fi & 15;
        cpa16(sb + SM_P0 + row * 256 + seg * 16,
              points + (size_t)(b * 1024 + row) * NN + n0 + seg * 4);
    }
    {
        int o = tid >> 3, sg = tid & 7;
        uint32_t sw = SWZ((uint32_t)(o * 128 + sg * 16));
        cpa16(sb + SM_B0H + sw, g_lw_hi + o * 1024 + sg * 8);
        cpa16(sb + SM_B0L + sw, g_lw_lo + o * 1024 + sg * 8);
    }
    cpa_commit();
    cpa_wait0();
    __syncthreads();

    // ---- weightnet: thread (m, og) owns o' = og*2 + {0,1} ----
    const int m  = tid >> 3;              // 0..63
    const int og = tid & 7;               // 0..7
    float wq[2][16];
    {
        const float* cs = (const float*)(smem + SM_P1);
        float w1r[2][3], b1r[2];
#pragma unroll
        for (int oo = 0; oo < 2; oo++) {
            int o = og * 2 + oo;
            w1r[oo][0] = w1[o * 3 + 0];
            w1r[oo][1] = w1[o * 3 + 1];
            w1r[oo][2] = w1[o * 3 + 2];
            b1r[oo]    = b1[o];
        }
#pragma unroll
        for (int k = 0; k < 16; k++) {
            float c0 = cs[(k) * 64 + m];
            float c1 = cs[(16 + k) * 64 + m];
            float c2 = cs[(32 + k) * 64 + m];
#pragma unroll
            for (int oo = 0; oo < 2; oo++) {
                float v = fmaf(w1r[oo][2], c2,
                          fmaf(w1r[oo][1], c1,
                          fmaf(w1r[oo][0], c0, b1r[oo])));
                wq[oo][k] = fmaxf(v, 0.0f);
            }
        }
    }
    __syncthreads();   // coord reads done before P1 gets overwritten

    // ---- GEMM lane geometry (warp grid 4m x 4n) ----
    const int wm = wid & 3, wn = wid >> 2;
    const uint32_t a_row = (uint32_t)(wm * 16 + (lane & 15));
    const uint32_t a_cb  = (uint32_t)((lane >> 4) * 16);
    const uint32_t b_row = (uint32_t)(wn * 16 + ((lane >> 4) << 3) + (lane & 7));
    const uint32_t b_cb  = (uint32_t)(((lane >> 3) & 1) * 16);
    float acc[2][4] = {};

    // A STS base + row-swizzle term: full-offset SW128 == in-row ^ ((m&7)<<4)
    const uint32_t a_sts  = sb + SM_AHI + (uint32_t)(m * 128);
    const uint32_t a_rswz = (uint32_t)((m & 7) << 4);
    uint32_t pb = 0, cbb = 0;

    for (int ch = 0; ch < NCHUNK; ch++) {
        // prefetch P(ch+1), B(ch+1)
        if (ch + 1 < NCHUNK) {
            uint32_t pdst = sb + (pb ? SM_P0 : SM_P1);
#pragma unroll
            for (int s = 0; s < 2; s++) {
                int fi = tid + 512 * s;
                int row = fi >> 4, seg = fi & 15;
                cpa16(pdst + row * 256 + seg * 16,
                      points + (size_t)(b * 1024 + (ch + 1) * 64 + row) * NN
                             + n0 + seg * 4);
            }
            uint32_t bh = sb + (cbb ? SM_B0H : SM_B1H);
            int o = tid >> 3, sg = tid & 7;
            uint32_t sw = SWZ((uint32_t)(o * 128 + sg * 16));
            cpa16(bh + sw,        g_lw_hi + o * 1024 + (ch + 1) * 64 + sg * 8);
            cpa16(bh + 8192 + sw, g_lw_lo + o * 1024 + (ch + 1) * 64 + sg * 8);
            cpa_commit();
        }

        // ---- t-compute + bf16 split + swizzled STS ----
        const float* P = (const float*)(smem + (pb ? SM_P1 : SM_P0));
#pragma unroll
        for (int c = 0; c < 4; c++) {
            float a0 = 0.f, a1 = 0.f;
#pragma unroll
            for (int k = 0; k < 16; k++) {
                float p = P[(c * 16 + k) * 64 + m];
                a0 = fmaf(p, wq[0][k], a0);
                a1 = fmaf(p, wq[1][k], a1);
            }
            __nv_bfloat16 h0 = __float2bfloat16(a0);
            __nv_bfloat16 h1 = __float2bfloat16(a1);
            __nv_bfloat16 l0 = __float2bfloat16(a0 - __bfloat162float(h0));
            __nv_bfloat16 l1 = __float2bfloat16(a1 - __bfloat162float(h1));
            uint32_t hp = (uint32_t)__bfloat16_as_ushort(h0)
                        | ((uint32_t)__bfloat16_as_ushort(h1) << 16);
            uint32_t lp = (uint32_t)__bfloat16_as_ushort(l0)
                        | ((uint32_t)__bfloat16_as_ushort(l1) << 16);
            uint32_t off = ((uint32_t)(c * 32 + og * 4)) ^ a_rswz;
            asm volatile("st.shared.b32 [%0], %1;" :: "r"(a_sts + off), "r"(hp) : "memory");
            asm volatile("st.shared.b32 [%0], %1;" :: "r"(a_sts + 8192 + off), "r"(lp) : "memory");
        }
        __syncthreads();

        // ---- warp GEMM: 4 k-steps x (ah*bh + ah*bl + al*bh) ----
        uint32_t bhb = sb + (cbb ? SM_B1H : SM_B0H);
#pragma unroll
        for (int ks = 0; ks < 4; ks++) {
            uint32_t aaddr = sb + SM_AHI + SWZ(a_row * 128 + ks * 32 + a_cb);
            uint32_t baddr = bhb + SWZ(b_row * 128 + ks * 32 + b_cb);
            uint32_t ah0, ah1, ah2, ah3, al0, al1, al2, al3;
            uint32_t bh0, bh1, bh2, bh3, bl0, bl1, bl2, bl3;
            LDSM4(ah0, ah1, ah2, ah3, aaddr);
            LDSM4(al0, al1, al2, al3, aaddr + 8192);
            LDSM4(bh0, bh1, bh2, bh3, baddr);
            LDSM4(bl0, bl1, bl2, bl3, baddr + 8192);
            MMA16816(acc[0], ah0, ah1, ah2, ah3, bh0, bh1);
            MMA16816(acc[1], ah0, ah1, ah2, ah3, bh2, bh3);
            MMA16816(acc[0], ah0, ah1, ah2, ah3, bl0, bl1);
            MMA16816(acc[1], ah0, ah1, ah2, ah3, bl2, bl3);
            MMA16816(acc[0], al0, al1, al2, al3, bh0, bh1);
            MMA16816(acc[1], al0, al1, al2, al3, bh2, bh3);
        }
        if (ch + 1 < NCHUNK) cpa_wait0();
        __syncthreads();
        pb ^= 1; cbb ^= 1;
    }

    // ---- epilogue: c-frags -> Ds[o][m] (+lin_b) ----
    float* Ds = (float*)(smem + SM_DS);
    const float* lb = (const float*)(smem + SM_LB);
    {
        int mlo = wm * 16 + (lane >> 2);
#pragma unroll
        for (int nb = 0; nb < 2; nb++) {
            int o0 = wn * 16 + nb * 8 + 2 * (lane & 3);
            Ds[o0 * 68 + mlo]           = acc[nb][0] + lb[o0];
            Ds[(o0 + 1) * 68 + mlo]     = acc[nb][1] + lb[o0 + 1];
            Ds[o0 * 68 + mlo + 8]       = acc[nb][2] + lb[o0];
            Ds[(o0 + 1) * 68 + mlo + 8] = acc[nb][3] + lb[o0 + 1];
        }
    }
    __syncthreads();

    // coalesced stores + deterministic BN partials
    {
        int o = tid >> 3, mseg = tid & 7;
        const float* src = Ds + o * 68 + mseg * 8;
        float4 v0 = *(const float4*)(src);
        float4 v1 = *(const float4*)(src + 4);
        float* dst = outp + ((size_t)(b * 64 + o) << 14) + n0 + mseg * 8;
        ((float4*)dst)[0] = v0;
        ((float4*)dst)[1] = v1;
        float s = v0.x + v0.y + v0.z + v0.w + v1.x + v1.y + v1.z + v1.w;
        float q = v0.x * v0.x + v0.y * v0.y + v0.z * v0.z + v0.w * v0.w
                + v1.x * v1.x + v1.y * v1.y + v1.z * v1.z + v1.w * v1.w;
        float* part = (float*)(smem + SM_PART);
        part[mseg * 64 + o]       = s;
        part[512 + mseg * 64 + o] = q;
    }
    __syncthreads();
    if (tid < 64) {
        const float* part = (const float*)(smem + SM_PART);
        float s = 0.f, q = 0.f;
#pragma unroll
        for (int g = 0; g < 8; g++) {
            s += part[g * 64 + tid];
            q += part[512 + g * 64 + tid];
        }
        g_psum[bx * 64 + tid] = s;
        g_psq[bx * 64 + tid]  = q;
    }
}

// ---------------------------------------------------------------------------
// k2: reduce 1024 partials per channel -> BN scale/shift
// ---------------------------------------------------------------------------
__global__ void sc_k2(const float* __restrict__ gamma,
                      const float* __restrict__ beta)
{
    const int ch = blockIdx.x;
    const int r  = threadIdx.x;      // 128
    float s = 0.f, q = 0.f;
    for (int c = r; c < NCTA; c += 128) {
        s += g_psum[c * 64 + ch];
        q += g_psq[c * 64 + ch];
    }
    __shared__ float ss[128], qs[128];
    ss[r] = s; qs[r] = q;
    __syncthreads();
    for (int d = 64; d; d >>= 1) {
        if (r < d) { ss[r] += ss[r + d]; qs[r] += qs[r + d]; }
        __syncthreads();
    }
    if (r == 0) {
        const float inv = 1.0f / (float)(NB * NN);
        float mean = ss[0] * inv;
        float var  = qs[0] * inv - mean * mean;
        float sc   = gamma[ch] * rsqrtf(var + 1e-5f);
        g_bn[ch]      = sc;
        g_bn[64 + ch] = beta[ch] - mean * sc;
    }
}

// ---------------------------------------------------------------------------
// k3: in-place BN + ReLU, float4
// ---------------------------------------------------------------------------
__global__ void sc_k3(float* __restrict__ outp)
{
    int i4 = blockIdx.x * blockDim.x + threadIdx.x;
    int ch = (i4 >> 12) & 63;
    float sc = g_bn[ch];
    float sh = g_bn[64 + ch];
    float4 v = reinterpret_cast<float4*>(outp)[i4];
    v.x = fmaxf(fmaf(v.x, sc, sh), 0.0f);
    v.y = fmaxf(fmaf(v.y, sc, sh), 0.0f);
    v.z = fmaxf(fmaf(v.z, sc, sh), 0.0f);
    v.w = fmaxf(fmaf(v.w, sc, sh), 0.0f);
    reinterpret_cast<float4*>(outp)[i4] = v;
}

// ---------------------------------------------------------------------------
extern "C" void kernel_launch(void* const* d_in, const int* in_sizes, int n_in,
                              void* d_out, int out_size)
{
    const float* xyz    = (const float*)d_in[0];
    const float* points = (const float*)d_in[1];
    const float* coord  = (const float*)d_in[2];
    const float* w1     = (const float*)d_in[3];
    const float* b1     = (const float*)d_in[4];
    const float* lin_w  = (const float*)d_in[5];
    const float* lin_b  = (const float*)d_in[6];
    const float* gamma  = (const float*)d_in[7];
    const float* beta   = (const float*)d_in[8];

    float* out = (float*)d_out;
    int off = out_size - OUT_ELEMS;
    if (off < 0) off = 0;
    float* outp = out + off;

    cudaFuncSetAttribute(sc_k1, cudaFuncAttributeMaxDynamicSharedMemorySize,
                         SM_TOTAL);

    if (off > 0) {
        cudaMemcpyAsync(out, xyz, (size_t)off * sizeof(float),
                        cudaMemcpyDeviceToDevice);
    }
    sc_k0<<<64, 256>>>(lin_w);
    sc_k1<<<NCTA, 512, SM_TOTAL>>>(points, coord, w1, b1, lin_b, outp);
    sc_k2<<<64, 128>>>(gamma, beta);
    sc_k3<<<OUT_ELEMS / 4 / 256, 256>>>(outp);
}

// round 7
// speedup vs baseline: 3.5270x; 1.1066x over previous
#include <cuda_runtime.h>
#include <cuda_bf16.h>
#include <stdint.h>

// B=4, C=64, K=16, N=16384, W_OUT=16, C_OUT=64
#define NB 4
#define NC 64
#define NN 16384
#define NCTA 1024                // 64 points per CTA
#define OUT_ELEMS (NB * NC * NN)
#define NCHUNK 16                // 4 channels/chunk -> kk=64

// ---- dynamic smem layout (bytes) ----
#define SM_LB    0                   // 64 floats (pad to 1024)
#define SM_A     1024                // 2 x (hi 8K + lo 8K) = 32K  [A tiles]
#define SM_B     (SM_A + 32768)      // 3 x (hi 8K + lo 8K) = 48K  [B tiles]
#define SM_P     (SM_B + 49152)      // 2 x 16K = 32K              [P stages]
#define SM_TOTAL (SM_P + 32768)      // 114688 B
// epilogue aliases
#define SM_DS    SM_P                // 64 o x 68 floats
#define SM_PART  SM_B                // 2 x 8 x 64 floats
// coord staged into A region during prologue (12KB < 16KB)
#define SM_COORD SM_A

__device__ float g_psum[NCTA * NC];
__device__ float g_psq[NCTA * NC];
__device__ float g_bn[2 * NC];
__device__ __align__(16) __nv_bfloat16 g_lw_hi[NC * 1024];  // [o][k]
__device__ __align__(16) __nv_bfloat16 g_lw_lo[NC * 1024];

#define SWZ(x) ((x) ^ (((x) >> 3) & 0x70))

static __device__ __forceinline__ uint32_t s2u(const void* p) {
    uint32_t a;
    asm("{ .reg .u64 t; cvta.to.shared.u64 t, %1; cvt.u32.u64 %0, t; }"
        : "=r"(a) : "l"(p));
    return a;
}
static __device__ __forceinline__ void cpa16(uint32_t dst, const void* src) {
    asm volatile("cp.async.cg.shared.global [%0], [%1], 16;"
                 :: "r"(dst), "l"(src) : "memory");
}
static __device__ __forceinline__ void cpa_commit() {
    asm volatile("cp.async.commit_group;" ::: "memory");
}
static __device__ __forceinline__ void cpa_wait0() {
    asm volatile("cp.async.wait_group 0;" ::: "memory");
}
static __device__ __forceinline__ void cpa_wait1() {
    asm volatile("cp.async.wait_group 1;" ::: "memory");
}

#define LDSM4(r0, r1, r2, r3, addr)                                          \
    asm volatile("ldmatrix.sync.aligned.m8n8.x4.shared.b16 {%0,%1,%2,%3}, [%4];" \
                 : "=r"(r0), "=r"(r1), "=r"(r2), "=r"(r3) : "r"(addr))

#define MMA16816(d, a0, a1, a2, a3, b0, b1)                                  \
    asm volatile("mma.sync.aligned.m16n8k16.row.col.f32.bf16.bf16.f32 "      \
                 "{%0,%1,%2,%3}, {%4,%5,%6,%7}, {%8,%9}, {%0,%1,%2,%3};"     \
                 : "+f"(d[0]), "+f"(d[1]), "+f"(d[2]), "+f"(d[3])            \
                 : "r"(a0), "r"(a1), "r"(a2), "r"(a3), "r"(b0), "r"(b1))

// pack two floats to bf16x2 (lo = a0, hi = a1)
static __device__ __forceinline__ uint32_t bf2pack(float a0, float a1) {
    uint32_t r;
    asm("cvt.rn.bf16x2.f32 %0, %1, %2;" : "=r"(r) : "f"(a1), "f"(a0));
    return r;
}

// ---------------------------------------------------------------------------
// k0: lin_w fp32 -> bf16 hi/lo tables, [o][k] k-major
// ---------------------------------------------------------------------------
__global__ void sc_k0(const float* __restrict__ lin_w) {
    int o = blockIdx.x;
    for (int k = threadIdx.x; k < 1024; k += 256) {
        float f = lin_w[o * 1024 + k];
        __nv_bfloat16 h = __float2bfloat16(f);
        float r = f - __bfloat162float(h);
        g_lw_hi[o * 1024 + k] = h;
        g_lw_lo[o * 1024 + k] = __float2bfloat16(r);
    }
}

// ---------------------------------------------------------------------------
// k1: fused weightnet + t-compute + bf16-split mma.sync GEMM, software-
// pipelined: GEMM(ch) overlaps t-compute(ch+1). CTA = 64 points, 512 thr.
// ---------------------------------------------------------------------------
__global__ __launch_bounds__(512, 1)
void sc_k1(const float* __restrict__ points,   // [B,64,16,N]
           const float* __restrict__ coord,    // [B,3,16,N]
           const float* __restrict__ w1,       // [16,3]
           const float* __restrict__ b1,       // [16]
           const float* __restrict__ lin_b,    // [64]
           float* __restrict__ outp)           // [B,64,N] pre-BN
{
    extern __shared__ char smem[];
    const uint32_t sb = s2u(smem);
    const int tid  = threadIdx.x;
    const int lane = tid & 31;
    const int wid  = tid >> 5;
    const int bx   = blockIdx.x;
    const int b    = bx >> 8;             // 256 tiles per batch
    const int n0   = (bx & 255) << 6;

    if (tid < 64) ((float*)(smem + SM_LB))[tid] = lin_b[tid];

    const int po = tid >> 3, psg = tid & 7;            // B-stage mapping
    const uint32_t bswz = SWZ((uint32_t)(po * 128 + psg * 16));

    // ---- prologue group 1: coord -> A region, P(0) -> Pb0, B(0) -> Bb0 ----
#pragma unroll
    for (int s = 0; s < 2; s++) {
        int fi = tid + 512 * s;           // coord: 768 x 16B
        if (fi < 768) {
            int row = fi >> 4, seg = fi & 15;
            cpa16(sb + SM_COORD + row * 256 + seg * 16,
                  coord + (size_t)(b * 48 + row) * NN + n0 + seg * 4);
        }
    }
#pragma unroll
    for (int s = 0; s < 2; s++) {
        int fi = tid + 512 * s;           // P: 1024 x 16B
        int row = fi >> 4, seg = fi & 15;
        cpa16(sb + SM_P + row * 256 + seg * 16,
              points + (size_t)(b * 1024 + row) * NN + n0 + seg * 4);
    }
    cpa16(sb + SM_B + bswz,        g_lw_hi + po * 1024 + psg * 8);
    cpa16(sb + SM_B + 8192 + bswz, g_lw_lo + po * 1024 + psg * 8);
    cpa_commit();

    // ---- prologue group 2: P(1) -> Pb1, B(1) -> Bb1 ----
#pragma unroll
    for (int s = 0; s < 2; s++) {
        int fi = tid + 512 * s;
        int row = fi >> 4, seg = fi & 15;
        cpa16(sb + SM_P + 16384 + row * 256 + seg * 16,
              points + (size_t)(b * 1024 + 64 + row) * NN + n0 + seg * 4);
    }
    cpa16(sb + SM_B + 16384 + bswz,        g_lw_hi + po * 1024 + 64 + psg * 8);
    cpa16(sb + SM_B + 16384 + 8192 + bswz, g_lw_lo + po * 1024 + 64 + psg * 8);
    cpa_commit();

    cpa_wait1();                          // group 1 (coord, P0, B0) done
    __syncthreads();

    // ---- weightnet: thread (m, og) owns o' = og*2 + {0,1} ----
    const int m  = tid >> 3;              // 0..63
    const int og = tid & 7;               // 0..7
    float wq[2][16];
    {
        const float* cs = (const float*)(smem + SM_COORD);
        float w1r[2][3], b1r[2];
#pragma unroll
        for (int oo = 0; oo < 2; oo++) {
            int o = og * 2 + oo;
            w1r[oo][0] = w1[o * 3 + 0];
            w1r[oo][1] = w1[o * 3 + 1];
            w1r[oo][2] = w1[o * 3 + 2];
            b1r[oo]    = b1[o];
        }
#pragma unroll
        for (int k = 0; k < 16; k++) {
            float c0 = cs[(k) * 64 + m];
            float c1 = cs[(16 + k) * 64 + m];
            float c2 = cs[(32 + k) * 64 + m];
#pragma unroll
            for (int oo = 0; oo < 2; oo++) {
                float v = fmaf(w1r[oo][2], c2,
                          fmaf(w1r[oo][1], c1,
                          fmaf(w1r[oo][0], c0, b1r[oo])));
                wq[oo][k] = fmaxf(v, 0.0f);
            }
        }
    }
    __syncthreads();   // coord reads done before A0 STS overwrites region

    // ---- lane geometry ----
    const int wm = wid & 3, wn = wid >> 2;
    const uint32_t a_row = (uint32_t)(wm * 16 + (lane & 15));
    const uint32_t a_cb  = (uint32_t)((lane >> 4) * 16);
    const uint32_t b_row = (uint32_t)(wn * 16 + ((lane >> 4) << 3) + (lane & 7));
    const uint32_t b_cb  = (uint32_t)(((lane >> 3) & 1) * 16);
    const uint32_t a_rswz = (uint32_t)((m & 7) << 4);
    float acc[2][4] = {};

    // ---- t-compute(0) -> A[0] ----
    {
        const float* P = (const float*)(smem + SM_P);
        uint32_t a_sts = sb + SM_A + (uint32_t)(m * 128);
#pragma unroll
        for (int c = 0; c < 4; c++) {
            float a0 = 0.f, a1 = 0.f;
#pragma unroll
            for (int k = 0; k < 16; k++) {
                float p = P[(c * 16 + k) * 64 + m];
                a0 = fmaf(p, wq[0][k], a0);
                a1 = fmaf(p, wq[1][k], a1);
            }
            uint32_t hp = bf2pack(a0, a1);
            float l0 = a0 - __uint_as_float(hp << 16);
            float l1 = a1 - __uint_as_float(hp & 0xffff0000u);
            uint32_t lp = bf2pack(l0, l1);
            uint32_t off = ((uint32_t)(c * 32 + og * 4)) ^ a_rswz;
            asm volatile("st.shared.b32 [%0], %1;" :: "r"(a_sts + off), "r"(hp) : "memory");
            asm volatile("st.shared.b32 [%0], %1;" :: "r"(a_sts + 8192 + off), "r"(lp) : "memory");
        }
    }
    __syncthreads();

    // ---- pipelined main loop ----
    for (int ch = 0; ch < NCHUNK; ch++) {
        // prefetch P(ch+2), B(ch+2)
        if (ch + 2 < NCHUNK) {
            uint32_t pdst = sb + SM_P + (uint32_t)((ch & 1) * 16384);
#pragma unroll
            for (int s = 0; s < 2; s++) {
                int fi = tid + 512 * s;
                int row = fi >> 4, seg = fi & 15;
                cpa16(pdst + row * 256 + seg * 16,
                      points + (size_t)(b * 1024 + (ch + 2) * 64 + row) * NN
                             + n0 + seg * 4);
            }
            uint32_t bdst = sb + SM_B + (uint32_t)(((ch + 2) % 3) * 16384);
            cpa16(bdst + bswz,        g_lw_hi + po * 1024 + (ch + 2) * 64 + psg * 8);
            cpa16(bdst + 8192 + bswz, g_lw_lo + po * 1024 + (ch + 2) * 64 + psg * 8);
            cpa_commit();
        }

        // ---- GEMM on A[ch&1] x B[ch%3] ----
        {
            uint32_t abase = sb + SM_A + (uint32_t)((ch & 1) * 16384);
            uint32_t bbase = sb + SM_B + (uint32_t)((ch % 3) * 16384);
#pragma unroll
            for (int ks = 0; ks < 4; ks++) {
                uint32_t aaddr = abase + SWZ(a_row * 128 + ks * 32 + a_cb);
                uint32_t baddr = bbase + SWZ(b_row * 128 + ks * 32 + b_cb);
                uint32_t ah0, ah1, ah2, ah3, al0, al1, al2, al3;
                uint32_t bh0, bh1, bh2, bh3, bl0, bl1, bl2, bl3;
                LDSM4(ah0, ah1, ah2, ah3, aaddr);
                LDSM4(al0, al1, al2, al3, aaddr + 8192);
                LDSM4(bh0, bh1, bh2, bh3, baddr);
                LDSM4(bl0, bl1, bl2, bl3, baddr + 8192);
                MMA16816(acc[0], ah0, ah1, ah2, ah3, bh0, bh1);
                MMA16816(acc[1], ah0, ah1, ah2, ah3, bh2, bh3);
                MMA16816(acc[0], ah0, ah1, ah2, ah3, bl0, bl1);
                MMA16816(acc[1], ah0, ah1, ah2, ah3, bl2, bl3);
                MMA16816(acc[0], al0, al1, al2, al3, bh0, bh1);
                MMA16816(acc[1], al0, al1, al2, al3, bh2, bh3);
            }
        }

        // ---- t-compute(ch+1) -> A[(ch+1)&1], overlaps the GEMM above ----
        if (ch + 1 < NCHUNK) {
            if (ch + 2 < NCHUNK) cpa_wait1();   // P/B(ch+1) landed
            else                 cpa_wait0();
            const float* P = (const float*)(smem + SM_P
                                            + ((ch + 1) & 1) * 16384);
            uint32_t a_sts = sb + SM_A + (uint32_t)(((ch + 1) & 1) * 16384)
                           + (uint32_t)(m * 128);
#pragma unroll
            for (int c = 0; c < 4; c++) {
                float a0 = 0.f, a1 = 0.f;
#pragma unroll
                for (int k = 0; k < 16; k++) {
                    float p = P[(c * 16 + k) * 64 + m];
                    a0 = fmaf(p, wq[0][k], a0);
                    a1 = fmaf(p, wq[1][k], a1);
                }
                uint32_t hp = bf2pack(a0, a1);
                float l0 = a0 - __uint_as_float(hp << 16);
                float l1 = a1 - __uint_as_float(hp & 0xffff0000u);
                uint32_t lp = bf2pack(l0, l1);
                uint32_t off = ((uint32_t)(c * 32 + og * 4)) ^ a_rswz;
                asm volatile("st.shared.b32 [%0], %1;" :: "r"(a_sts + off), "r"(hp) : "memory");
                asm volatile("st.shared.b32 [%0], %1;" :: "r"(a_sts + 8192 + off), "r"(lp) : "memory");
            }
        }
        __syncthreads();
    }

    // ---- epilogue: c-frags -> Ds[o][m] (+lin_b) ----
    float* Ds = (float*)(smem + SM_DS);
    const float* lb = (const float*)(smem + SM_LB);
    {
        int mlo = wm * 16 + (lane >> 2);
#pragma unroll
        for (int nb = 0; nb < 2; nb++) {
            int o0 = wn * 16 + nb * 8 + 2 * (lane & 3);
            Ds[o0 * 68 + mlo]           = acc[nb][0] + lb[o0];
            Ds[(o0 + 1) * 68 + mlo]     = acc[nb][1] + lb[o0 + 1];
            Ds[o0 * 68 + mlo + 8]       = acc[nb][2] + lb[o0];
            Ds[(o0 + 1) * 68 + mlo + 8] = acc[nb][3] + lb[o0 + 1];
        }
    }
    __syncthreads();

    // coalesced stores + deterministic BN partials
    {
        int o = tid >> 3, mseg = tid & 7;
        const float* src = Ds + o * 68 + mseg * 8;
        float4 v0 = *(const float4*)(src);
        float4 v1 = *(const float4*)(src + 4);
        float* dst = outp + ((size_t)(b * 64 + o) << 14) + n0 + mseg * 8;
        ((float4*)dst)[0] = v0;
        ((float4*)dst)[1] = v1;
        float s = v0.x + v0.y + v0.z + v0.w + v1.x + v1.y + v1.z + v1.w;
        float q = v0.x * v0.x + v0.y * v0.y + v0.z * v0.z + v0.w * v0.w
                + v1.x * v1.x + v1.y * v1.y + v1.z * v1.z + v1.w * v1.w;
        float* part = (float*)(smem + SM_PART);
        part[mseg * 64 + o]       = s;
        part[512 + mseg * 64 + o] = q;
    }
    __syncthreads();
    if (tid < 64) {
        const float* part = (const float*)(smem + SM_PART);
        float s = 0.f, q = 0.f;
#pragma unroll
        for (int g = 0; g < 8; g++) {
            s += part[g * 64 + tid];
            q += part[512 + g * 64 + tid];
        }
        g_psum[bx * 64 + tid] = s;
        g_psq[bx * 64 + tid]  = q;
    }
}

// ---------------------------------------------------------------------------
// k2: reduce 1024 partials per channel -> BN scale/shift
// ---------------------------------------------------------------------------
__global__ void sc_k2(const float* __restrict__ gamma,
                      const float* __restrict__ beta)
{
    const int ch = blockIdx.x;
    const int r  = threadIdx.x;      // 128
    float s = 0.f, q = 0.f;
    for (int c = r; c < NCTA; c += 128) {
        s += g_psum[c * 64 + ch];
        q += g_psq[c * 64 + ch];
    }
    __shared__ float ss[128], qs[128];
    ss[r] = s; qs[r] = q;
    __syncthreads();
    for (int d = 64; d; d >>= 1) {
        if (r < d) { ss[r] += ss[r + d]; qs[r] += qs[r + d]; }
        __syncthreads();
    }
    if (r == 0) {
        const float inv = 1.0f / (float)(NB * NN);
        float mean = ss[0] * inv;
        float var  = qs[0] * inv - mean * mean;
        float sc   = gamma[ch] * rsqrtf(var + 1e-5f);
        g_bn[ch]      = sc;
        g_bn[64 + ch] = beta[ch] - mean * sc;
    }
}

// ---------------------------------------------------------------------------
// k3: in-place BN + ReLU, float4
// ---------------------------------------------------------------------------
__global__ void sc_k3(float* __restrict__ outp)
{
    int i4 = blockIdx.x * blockDim.x + threadIdx.x;
    int ch = (i4 >> 12) & 63;
    float sc = g_bn[ch];
    float sh = g_bn[64 + ch];
    float4 v = reinterpret_cast<float4*>(outp)[i4];
    v.x = fmaxf(fmaf(v.x, sc, sh), 0.0f);
    v.y = fmaxf(fmaf(v.y, sc, sh), 0.0f);
    v.z = fmaxf(fmaf(v.z, sc, sh), 0.0f);
    v.w = fmaxf(fmaf(v.w, sc, sh), 0.0f);
    reinterpret_cast<float4*>(outp)[i4] = v;
}

// ---------------------------------------------------------------------------
extern "C" void kernel_launch(void* const* d_in, const int* in_sizes, int n_in,
                              void* d_out, int out_size)
{
    const float* xyz    = (const float*)d_in[0];
    const float* points = (const float*)d_in[1];
    const float* coord  = (const float*)d_in[2];
    const float* w1     = (const float*)d_in[3];
    const float* b1     = (const float*)d_in[4];
    const float* lin_w  = (const float*)d_in[5];
    const float* lin_b  = (const float*)d_in[6];
    const float* gamma  = (const float*)d_in[7];
    const float* beta   = (const float*)d_in[8];

    float* out = (float*)d_out;
    int off = out_size - OUT_ELEMS;
    if (off < 0) off = 0;
    float* outp = out + off;

    cudaFuncSetAttribute(sc_k1, cudaFuncAttributeMaxDynamicSharedMemorySize,
                         SM_TOTAL);

    if (off > 0) {
        cudaMemcpyAsync(out, xyz, (size_t)off * sizeof(float),
                        cudaMemcpyDeviceToDevice);
    }
    sc_k0<<<64, 256>>>(lin_w);
    sc_k1<<<NCTA, 512, SM_TOTAL>>>(points, coord, w1, b1, lin_b, outp);
    sc_k2<<<64, 128>>>(gamma, beta);
    sc_k3<<<OUT_ELEMS / 4 / 256, 256>>>(outp);
}

// round 8
// speedup vs baseline: 4.1144x; 1.1665x over previous
#include <cuda_runtime.h>
#include <cuda_bf16.h>
#include <stdint.h>

// B=4, C=64, K=16, N=16384, W_OUT=16, C_OUT=64
#define NB 4
#define NC 64
#define NN 16384
#define NCTA 1024                // 64 points per CTA
#define OUT_ELEMS (NB * NC * NN)
#define NCHUNK 16                // 4 channels/chunk -> kk=64

// ---- dynamic smem layout (bytes) ----
#define SM_LB    0                    // 64 floats (pad to 1024)
#define SM_A     1024                 // 2 x (hi 8K + lo 8K) = 32K
#define SM_COORD (SM_A + 16384)       // aliases A[1]; 48 rows x 256B = 12K
#define SM_B     (SM_A + 32768)       // 2 x (hi 8K + lo 8K) = 32K
#define SM_P     (SM_B + 32768)       // 2 x 16K = 32K
#define SM_TOTAL (SM_P + 32768)       // 99328 B
// epilogue aliases
#define SM_DS    SM_P                 // 64 o x 68 floats
#define SM_PART  SM_B                 // 2 x 8 x 64 floats

// named barriers
#define BFULL0 1
#define BFULL1 2
#define BEMPTY0 3
#define BEMPTY1 4
#define BPROD 5
#define BCONS 6

__device__ float g_psum[NCTA * NC];
__device__ float g_psq[NCTA * NC];
__device__ float g_bn[2 * NC];
__device__ __align__(16) __nv_bfloat16 g_lw_hi[NC * 1024];  // [o][k]
__device__ __align__(16) __nv_bfloat16 g_lw_lo[NC * 1024];

#define SWZ(x) ((x) ^ (((x) >> 3) & 0x70))

static __device__ __forceinline__ uint32_t s2u(const void* p) {
    uint32_t a;
    asm("{ .reg .u64 t; cvta.to.shared.u64 t, %1; cvt.u32.u64 %0, t; }"
        : "=r"(a) : "l"(p));
    return a;
}
static __device__ __forceinline__ void cpa16(uint32_t dst, const void* src) {
    asm volatile("cp.async.cg.shared.global [%0], [%1], 16;"
                 :: "r"(dst), "l"(src) : "memory");
}
static __device__ __forceinline__ void cpa_commit() {
    asm volatile("cp.async.commit_group;" ::: "memory");
}
static __device__ __forceinline__ void cpa_wait0() {
    asm volatile("cp.async.wait_group 0;" ::: "memory");
}
static __device__ __forceinline__ void cpa_wait1() {
    asm volatile("cp.async.wait_group 1;" ::: "memory");
}
#define BAR_SYNC(id, cnt)  asm volatile("bar.sync %0, %1;"   :: "r"(id), "r"(cnt) : "memory")
#define BAR_ARRIVE(id, cnt) asm volatile("bar.arrive %0, %1;" :: "r"(id), "r"(cnt) : "memory")

#define LDSM4(r0, r1, r2, r3, addr)                                          \
    asm volatile("ldmatrix.sync.aligned.m8n8.x4.shared.b16 {%0,%1,%2,%3}, [%4];" \
                 : "=r"(r0), "=r"(r1), "=r"(r2), "=r"(r3) : "r"(addr))

#define MMA16816(d, a0, a1, a2, a3, b0, b1)                                  \
    asm volatile("mma.sync.aligned.m16n8k16.row.col.f32.bf16.bf16.f32 "      \
                 "{%0,%1,%2,%3}, {%4,%5,%6,%7}, {%8,%9}, {%0,%1,%2,%3};"     \
                 : "+f"(d[0]), "+f"(d[1]), "+f"(d[2]), "+f"(d[3])            \
                 : "r"(a0), "r"(a1), "r"(a2), "r"(a3), "r"(b0), "r"(b1))

static __device__ __forceinline__ uint32_t bf2pack(float a0, float a1) {
    uint32_t r;
    asm("cvt.rn.bf16x2.f32 %0, %1, %2;" : "=r"(r) : "f"(a1), "f"(a0));
    return r;
}

// ---------------------------------------------------------------------------
// k0: lin_w fp32 -> bf16 hi/lo tables, [o][k] k-major
// ---------------------------------------------------------------------------
__global__ void sc_k0(const float* __restrict__ lin_w) {
    int o = blockIdx.x;
    for (int k = threadIdx.x; k < 1024; k += 256) {
        float f = lin_w[o * 1024 + k];
        __nv_bfloat16 h = __float2bfloat16(f);
        float r = f - __bfloat162float(h);
        g_lw_hi[o * 1024 + k] = h;
        g_lw_lo[o * 1024 + k] = __float2bfloat16(r);
    }
}

// ---------------------------------------------------------------------------
// k1: warp-specialized. Warps 0-7 produce A tiles (weightnet + t-compute),
// warps 8-15 consume (bf16-split mma.sync GEMM). CTA = 64 points, 512 thr.
// ---------------------------------------------------------------------------
__global__ __launch_bounds__(512, 1)
void sc_k1(const float* __restrict__ points,   // [B,64,16,N]
           const float* __restrict__ coord,    // [B,3,16,N]
           const float* __restrict__ w1,       // [16,3]
           const float* __restrict__ b1,       // [16]
           const float* __restrict__ lin_b,    // [64]
           float* __restrict__ outp)           // [B,64,N] pre-BN
{
    extern __shared__ char smem[];
    const uint32_t sb = s2u(smem);
    const int tid  = threadIdx.x;
    const int lane = tid & 31;
    const int wid  = tid >> 5;
    const int bx   = blockIdx.x;
    const int bb   = bx >> 8;             // batch
    const int n0   = (bx & 255) << 6;

    if (tid < 64) ((float*)(smem + SM_LB))[tid] = lin_b[tid];

    if (wid < 8) {
        // =================== PRODUCER (256 threads) ===================
        const int tp = tid;               // 0..255
        // prologue G1: coord + P(0)
#pragma unroll
        for (int s = 0; s < 3; s++) {
            int fi = tp + 256 * s;        // 768 f4
            int row = fi >> 4, seg = fi & 15;
            cpa16(sb + SM_COORD + row * 256 + seg * 16,
                  coord + (size_t)(bb * 48 + row) * NN + n0 + seg * 4);
        }
#pragma unroll
        for (int s = 0; s < 4; s++) {
            int fi = tp + 256 * s;        // 1024 f4
            int row = fi >> 4, seg = fi & 15;
            cpa16(sb + SM_P + row * 256 + seg * 16,
                  points + (size_t)(bb * 1024 + row) * NN + n0 + seg * 4);
        }
        cpa_commit();
        // prologue G2: P(1)
#pragma unroll
        for (int s = 0; s < 4; s++) {
            int fi = tp + 256 * s;
            int row = fi >> 4, seg = fi & 15;
            cpa16(sb + SM_P + 16384 + row * 256 + seg * 16,
                  points + (size_t)(bb * 1024 + 64 + row) * NN + n0 + seg * 4);
        }
        cpa_commit();
        cpa_wait1();
        BAR_SYNC(BPROD, 256);             // coord + P0 visible

        // weightnet: thread (m, og) owns o' = og*4 + {0..3}
        const int m  = tp >> 2;           // 0..63
        const int og = tp & 3;            // 0..3
        float wq[4][16];
        {
            const float* cs = (const float*)(smem + SM_COORD);
            float w1r[4][3], b1r[4];
#pragma unroll
            for (int oo = 0; oo < 4; oo++) {
                int o = og * 4 + oo;
                w1r[oo][0] = w1[o * 3 + 0];
                w1r[oo][1] = w1[o * 3 + 1];
                w1r[oo][2] = w1[o * 3 + 2];
                b1r[oo]    = b1[o];
            }
#pragma unroll
            for (int k = 0; k < 16; k++) {
                float c0 = cs[(k) * 64 + m];
                float c1 = cs[(16 + k) * 64 + m];
                float c2 = cs[(32 + k) * 64 + m];
#pragma unroll
                for (int oo = 0; oo < 4; oo++) {
                    float v = fmaf(w1r[oo][2], c2,
                              fmaf(w1r[oo][1], c1,
                              fmaf(w1r[oo][0], c0, b1r[oo])));
                    wq[oo][k] = fmaxf(v, 0.0f);
                }
            }
        }

        const uint32_t a_rswz = (uint32_t)((m & 7) << 4);
        const uint32_t a_base = sb + SM_A + (uint32_t)(m * 128);

        for (int ch = 0; ch < NCHUNK; ch++) {
            const int buf = ch & 1;
            if (ch >= 2) BAR_SYNC(BEMPTY0 + buf, 512);
            if (ch + 2 < NCHUNK) cpa_wait1(); else cpa_wait0();
            BAR_SYNC(BPROD, 256);         // P(ch) visible to all producers

            const float* P = (const float*)(smem + SM_P + buf * 16384);
            uint32_t a_sts = a_base + (uint32_t)(buf * 16384);
#pragma unroll
            for (int c = 0; c < 4; c++) {
                float a0 = 0.f, a1 = 0.f, a2 = 0.f, a3 = 0.f;
#pragma unroll
                for (int k = 0; k < 16; k++) {
                    float p = P[(c * 16 + k) * 64 + m];
                    a0 = fmaf(p, wq[0][k], a0);
                    a1 = fmaf(p, wq[1][k], a1);
                    a2 = fmaf(p, wq[2][k], a2);
                    a3 = fmaf(p, wq[3][k], a3);
                }
                uint32_t hp0 = bf2pack(a0, a1);
                uint32_t hp1 = bf2pack(a2, a3);
                float l0 = a0 - __uint_as_float(hp0 << 16);
                float l1 = a1 - __uint_as_float(hp0 & 0xffff0000u);
                float l2 = a2 - __uint_as_float(hp1 << 16);
                float l3 = a3 - __uint_as_float(hp1 & 0xffff0000u);
                uint32_t lp0 = bf2pack(l0, l1);
                uint32_t lp1 = bf2pack(l2, l3);
                uint32_t off = ((uint32_t)(c * 32 + og * 8)) ^ a_rswz;
                asm volatile("st.shared.v2.b32 [%0], {%1, %2};"
                             :: "r"(a_sts + off), "r"(hp0), "r"(hp1) : "memory");
                asm volatile("st.shared.v2.b32 [%0], {%1, %2};"
                             :: "r"(a_sts + 8192 + off), "r"(lp0), "r"(lp1) : "memory");
            }
            BAR_ARRIVE(BFULL0 + buf, 512);
            BAR_SYNC(BPROD, 256);         // all producers done reading P(ch)
            if (ch + 2 < NCHUNK) {
                uint32_t pdst = sb + SM_P + (uint32_t)(buf * 16384);
#pragma unroll
                for (int s = 0; s < 4; s++) {
                    int fi = tp + 256 * s;
                    int row = fi >> 4, seg = fi & 15;
                    cpa16(pdst + row * 256 + seg * 16,
                          points + (size_t)(bb * 1024 + (ch + 2) * 64 + row) * NN
                                 + n0 + seg * 4);
                }
                cpa_commit();
            }
        }
    } else {
        // =================== CONSUMER (256 threads) ===================
        const int tc = tid - 256;         // 0..255
        const int po = tc >> 2;           // 0..63 (B row)
        // prologue: B(0), B(1)
#pragma unroll
        for (int cb = 0; cb < 2; cb++) {
            uint32_t bdst = sb + SM_B + (uint32_t)(cb * 16384);
#pragma unroll
            for (int j = 0; j < 2; j++) {
                int psg = (tc & 3) * 2 + j;
                uint32_t sw = SWZ((uint32_t)(po * 128 + psg * 16));
                cpa16(bdst + sw,        g_lw_hi + po * 1024 + cb * 64 + psg * 8);
                cpa16(bdst + 8192 + sw, g_lw_lo + po * 1024 + cb * 64 + psg * 8);
            }
            cpa_commit();
        }

        const int wc = wid - 8;           // 0..7
        const int wm = wc & 1, wn = wc >> 1;
        const uint32_t a_cb = (uint32_t)((lane >> 4) * 16);
        const uint32_t b_row = (uint32_t)(wn * 16 + ((lane >> 4) << 3) + (lane & 7));
        const uint32_t b_cb  = (uint32_t)(((lane >> 3) & 1) * 16);
        float acc[2][2][4] = {};

        for (int ch = 0; ch < NCHUNK; ch++) {
            const int buf = ch & 1;
            if (ch + 2 < NCHUNK) cpa_wait1(); else cpa_wait0();
            BAR_SYNC(BCONS, 256);         // B(ch) visible
            BAR_SYNC(BFULL0 + buf, 512);  // A(ch) ready

            uint32_t abase = sb + SM_A + (uint32_t)(buf * 16384);
            uint32_t bbase = sb + SM_B + (uint32_t)(buf * 16384);
#pragma unroll
            for (int ks = 0; ks < 4; ks++) {
                uint32_t bh0, bh1, bh2, bh3, bl0, bl1, bl2, bl3;
                uint32_t baddr = bbase + SWZ(b_row * 128 + ks * 32 + b_cb);
                LDSM4(bh0, bh1, bh2, bh3, baddr);
                LDSM4(bl0, bl1, bl2, bl3, baddr + 8192);
#pragma unroll
                for (int mt = 0; mt < 2; mt++) {
                    uint32_t a_row = (uint32_t)(wm * 32 + mt * 16 + (lane & 15));
                    uint32_t aaddr = abase + SWZ(a_row * 128 + ks * 32 + a_cb);
                    uint32_t ah0, ah1, ah2, ah3, al0, al1, al2, al3;
                    LDSM4(ah0, ah1, ah2, ah3, aaddr);
                    LDSM4(al0, al1, al2, al3, aaddr + 8192);
                    MMA16816(acc[mt][0], ah0, ah1, ah2, ah3, bh0, bh1);
                    MMA16816(acc[mt][1], ah0, ah1, ah2, ah3, bh2, bh3);
                    MMA16816(acc[mt][0], ah0, ah1, ah2, ah3, bl0, bl1);
                    MMA16816(acc[mt][1], ah0, ah1, ah2, ah3, bl2, bl3);
                    MMA16816(acc[mt][0], al0, al1, al2, al3, bh0, bh1);
                    MMA16816(acc[mt][1], al0, al1, al2, al3, bh2, bh3);
                }
            }
            BAR_ARRIVE(BEMPTY0 + buf, 512);
            BAR_SYNC(BCONS, 256);         // all consumers done reading B(ch)
            if (ch + 2 < NCHUNK) {
                uint32_t bdst = sb + SM_B + (uint32_t)(buf * 16384);
#pragma unroll
                for (int j = 0; j < 2; j++) {
                    int psg = (tc & 3) * 2 + j;
                    uint32_t sw = SWZ((uint32_t)(po * 128 + psg * 16));
                    cpa16(bdst + sw,        g_lw_hi + po * 1024 + (ch + 2) * 64 + psg * 8);
                    cpa16(bdst + 8192 + sw, g_lw_lo + po * 1024 + (ch + 2) * 64 + psg * 8);
                }
                cpa_commit();
            }
        }

        // stash c-frags -> Ds[o][m] (+lin_b) after all threads re-sync below
        __syncthreads();                  // (1) pairs with producer side below
        float* Ds = (float*)(smem + SM_DS);
        const float* lb = (const float*)(smem + SM_LB);
#pragma unroll
        for (int mt = 0; mt < 2; mt++) {
            int mlo = wm * 32 + mt * 16 + (lane >> 2);
#pragma unroll
            for (int nb = 0; nb < 2; nb++) {
                int o0 = wn * 16 + nb * 8 + 2 * (lane & 3);
                Ds[o0 * 68 + mlo]           = acc[mt][nb][0] + lb[o0];
                Ds[(o0 + 1) * 68 + mlo]     = acc[mt][nb][1] + lb[o0 + 1];
                Ds[o0 * 68 + mlo + 8]       = acc[mt][nb][2] + lb[o0];
                Ds[(o0 + 1) * 68 + mlo + 8] = acc[mt][nb][3] + lb[o0 + 1];
            }
        }
    }

    if (wid < 8) __syncthreads();         // (1) producer side
    __syncthreads();                      // (2) Ds complete for everyone

    // coalesced stores + deterministic BN partials (all 512 threads)
    {
        float* Ds = (float*)(smem + SM_DS);
        int o = tid >> 3, mseg = tid & 7;
        const float* src = Ds + o * 68 + mseg * 8;
        float4 v0 = *(const float4*)(src);
        float4 v1 = *(const float4*)(src + 4);
        float* dst = outp + ((size_t)(bb * 64 + o) << 14) + n0 + mseg * 8;
        ((float4*)dst)[0] = v0;
        ((float4*)dst)[1] = v1;
        float s = v0.x + v0.y + v0.z + v0.w + v1.x + v1.y + v1.z + v1.w;
        float q = v0.x * v0.x + v0.y * v0.y + v0.z * v0.z + v0.w * v0.w
                + v1.x * v1.x + v1.y * v1.y + v1.z * v1.z + v1.w * v1.w;
        float* part = (float*)(smem + SM_PART);
        part[mseg * 64 + o]       = s;
        part[512 + mseg * 64 + o] = q;
    }
    __syncthreads();
    if (tid < 64) {
        const float* part = (const float*)(smem + SM_PART);
        float s = 0.f, q = 0.f;
#pragma unroll
        for (int g = 0; g < 8; g++) {
            s += part[g * 64 + tid];
            q += part[512 + g * 64 + tid];
        }
        g_psum[bx * 64 + tid] = s;
        g_psq[bx * 64 + tid]  = q;
    }
}

// ---------------------------------------------------------------------------
// k2: reduce 1024 partials per channel -> BN scale/shift
// ---------------------------------------------------------------------------
__global__ void sc_k2(const float* __restrict__ gamma,
                      const float* __restrict__ beta)
{
    const int ch = blockIdx.x;
    const int r  = threadIdx.x;      // 128
    float s = 0.f, q = 0.f;
    for (int c = r; c < NCTA; c += 128) {
        s += g_psum[c * 64 + ch];
        q += g_psq[c * 64 + ch];
    }
    __shared__ float ss[128], qs[128];
    ss[r] = s; qs[r] = q;
    __syncthreads();
    for (int d = 64; d; d >>= 1) {
        if (r < d) { ss[r] += ss[r + d]; qs[r] += qs[r + d]; }
        __syncthreads();
    }
    if (r == 0) {
        const float inv = 1.0f / (float)(NB * NN);
        float mean = ss[0] * inv;
        float var  = qs[0] * inv - mean * mean;
        float sc   = gamma[ch] * rsqrtf(var + 1e-5f);
        g_bn[ch]      = sc;
        g_bn[64 + ch] = beta[ch] - mean * sc;
    }
}

// ---------------------------------------------------------------------------
// k3: in-place BN + ReLU, float4
// ---------------------------------------------------------------------------
__global__ void sc_k3(float* __restrict__ outp)
{
    int i4 = blockIdx.x * blockDim.x + threadIdx.x;
    int ch = (i4 >> 12) & 63;
    float sc = g_bn[ch];
    float sh = g_bn[64 + ch];
    float4 v = reinterpret_cast<float4*>(outp)[i4];
    v.x = fmaxf(fmaf(v.x, sc, sh), 0.0f);
    v.y = fmaxf(fmaf(v.y, sc, sh), 0.0f);
    v.z = fmaxf(fmaf(v.z, sc, sh), 0.0f);
    v.w = fmaxf(fmaf(v.w, sc, sh), 0.0f);
    reinterpret_cast<float4*>(outp)[i4] = v;
}

// ---------------------------------------------------------------------------
extern "C" void kernel_launch(void* const* d_in, const int* in_sizes, int n_in,
                              void* d_out, int out_size)
{
    const float* xyz    = (const float*)d_in[0];
    const float* points = (const float*)d_in[1];
    const float* coord  = (const float*)d_in[2];
    const float* w1     = (const float*)d_in[3];
    const float* b1     = (const float*)d_in[4];
    const float* lin_w  = (const float*)d_in[5];
    const float* lin_b  = (const float*)d_in[6];
    const float* gamma  = (const float*)d_in[7];
    const float* beta   = (const float*)d_in[8];

    float* out = (float*)d_out;
    int off = out_size - OUT_ELEMS;
    if (off < 0) off = 0;
    float* outp = out + off;

    cudaFuncSetAttribute(sc_k1, cudaFuncAttributeMaxDynamicSharedMemorySize,
                         SM_TOTAL);

    if (off > 0) {
        cudaMemcpyAsync(out, xyz, (size_t)off * sizeof(float),
                        cudaMemcpyDeviceToDevice);
    }
    sc_k0<<<64, 256>>>(lin_w);
    sc_k1<<<NCTA, 512, SM_TOTAL>>>(points, coord, w1, b1, lin_b, outp);
    sc_k2<<<64, 128>>>(gamma, beta);
    sc_k3<<<OUT_ELEMS / 4 / 256, 256>>>(outp);
}